// round 2
// baseline (speedup 1.0000x reference)
#include <cuda_runtime.h>
#include <math.h>

// ---------------------------------------------------------------------------
// B=8, CIN=64, COUT=64, H=W=128, R=2, HID=8, K=3, GK=15
// ---------------------------------------------------------------------------
#define BB   8
#define CIN  64
#define COUT 64
#define HH   128
#define WW   128
#define RR   2
#define HID  8
#define HW   (HH*WW)          // 16384

// ---------------------------------------------------------------------------
// Device scratch (no allocation allowed)
// ---------------------------------------------------------------------------
__device__ float g_pooled[BB*CIN*9];                 // [b][ci][yx]
// conv weights, layout [b][r][ci][kyx(9)][co]  (co fastest -> packed pairs)
__device__ float g_kern[(size_t)BB*RR*CIN*9*COUT];   // 589824 floats
__device__ float g_sa[BB*HW];
__device__ float g_pmin[BB*16];                      // per-tile sa min partials
__device__ float g_pmax[BB*16];

// ---------------------------------------------------------------------------
// 1) Adaptive avg pool 128x128 -> 3x3 (PyTorch bins: [0,43) [42,86) [85,128))
// ---------------------------------------------------------------------------
__global__ void pool_kernel(const float* __restrict__ feat) {
    const int bc = blockIdx.x;                 // b*64+ci
    const float* src = feat + (size_t)bc * HW;
    float a[9];
    #pragma unroll
    for (int i = 0; i < 9; ++i) a[i] = 0.f;

    for (int idx = threadIdx.x; idx < HW; idx += 128) {
        float v = src[idx];
        int y = idx >> 7, x = idx & 127;
        bool rm0 = (y < 43), rm1 = (y >= 42) & (y < 86), rm2 = (y >= 85);
        bool cm0 = (x < 43), cm1 = (x >= 42) & (x < 86), cm2 = (x >= 85);
        if (rm0) { if (cm0) a[0]+=v; if (cm1) a[1]+=v; if (cm2) a[2]+=v; }
        if (rm1) { if (cm0) a[3]+=v; if (cm1) a[4]+=v; if (cm2) a[5]+=v; }
        if (rm2) { if (cm0) a[6]+=v; if (cm1) a[7]+=v; if (cm2) a[8]+=v; }
    }

    __shared__ float red[9][128];
    #pragma unroll
    for (int k = 0; k < 9; ++k) red[k][threadIdx.x] = a[k];
    __syncthreads();
    for (int s = 64; s > 0; s >>= 1) {
        if (threadIdx.x < s) {
            #pragma unroll
            for (int k = 0; k < 9; ++k)
                red[k][threadIdx.x] += red[k][threadIdx.x + s];
        }
        __syncthreads();
    }
    if (threadIdx.x < 9) {
        const float cnt[3] = {43.f, 44.f, 43.f};
        int i = threadIdx.x / 3, j = threadIdx.x % 3;
        g_pooled[bc*9 + threadIdx.x] = red[threadIdx.x][0] / (cnt[i] * cnt[j]);
    }
}

// ---------------------------------------------------------------------------
// 2) Fused MLP1 + kernel generation.  Block = (b, r, yx), 144 blocks.
//    hid[h]  = sigmoid(b1[r*8+h] + sum_ci w1[r*8+h, ci] * pooled[b,ci,yx])
//    q = r*4096 + co*64 + ci
//    g_kern[((b*2+r)*64+ci)*576 + yx*64 + co] = b2[q] + sum_h w2[q*8+h]*hid[h]
// ---------------------------------------------------------------------------
__global__ void kerngen_kernel(const float* __restrict__ w1,
                               const float* __restrict__ b1,
                               const float* __restrict__ w2,
                               const float* __restrict__ b2) {
    const int blk = blockIdx.x;               // 0..143
    const int b = blk / 18, rem = blk % 18;
    const int r = rem / 9, yx = rem % 9;

    __shared__ float hs[8];
    if (threadIdx.x < 8) {
        const int c = r*8 + threadIdx.x;
        float v = b1[c];
        #pragma unroll 8
        for (int ci = 0; ci < CIN; ++ci)
            v += w1[c*CIN + ci] * g_pooled[(b*CIN + ci)*9 + yx];
        hs[threadIdx.x] = 1.f / (1.f + expf(-v));
    }
    __syncthreads();

    for (int idx = threadIdx.x; idx < CIN*COUT; idx += 256) {
        const int co = idx & 63, ci = idx >> 6;
        const int q = r*(CIN*COUT) + co*CIN + ci;
        const float* wp = w2 + (size_t)q * HID;
        float v = b2[q];
        #pragma unroll
        for (int h = 0; h < HID; ++h) v += wp[h] * hs[h];
        g_kern[((size_t)(b*2 + r)*CIN + ci)*576 + yx*64 + co] = v;
    }
}

// ---------------------------------------------------------------------------
// 3) Guide: sigmoid(pred) -> 15x15 gaussian conv -> per-tile min/max partials
// ---------------------------------------------------------------------------
__global__ __launch_bounds__(256) void sa_kernel(const float* __restrict__ pred,
                                                 const float* __restrict__ gk) {
    __shared__ float sp[46][46];
    __shared__ float sg[225];
    const int b  = blockIdx.z;
    const int x0 = blockIdx.x * 32, y0 = blockIdx.y * 32;
    const int tid = threadIdx.x;

    for (int i = tid; i < 225; i += 256) sg[i] = gk[i];
    for (int i = tid; i < 46*46; i += 256) {
        int ly = i / 46, lx = i % 46;
        int gy = y0 - 7 + ly, gx = x0 - 7 + lx;
        float v = 0.f;  // conv zero-pads the sigmoid'd input
        if ((unsigned)gy < 128u && (unsigned)gx < 128u) {
            float pv = pred[b*HW + gy*128 + gx];
            v = 1.f / (1.f + expf(-pv));
        }
        sp[ly][lx] = v;
    }
    __syncthreads();

    float tmn = 3.4e38f, tmx = 0.f;   // sa >= 0
    #pragma unroll
    for (int p = 0; p < 4; ++p) {
        int id = tid + p*256;
        int py = id >> 5, px = id & 31;
        float s = 0.f;
        for (int u = 0; u < 15; ++u) {
            #pragma unroll
            for (int v = 0; v < 15; ++v)
                s += sp[py + u][px + v] * sg[u*15 + v];
        }
        g_sa[b*HW + (y0 + py)*128 + (x0 + px)] = s;
        tmn = fminf(tmn, s); tmx = fmaxf(tmx, s);
    }
    #pragma unroll
    for (int o = 16; o; o >>= 1) {
        tmn = fminf(tmn, __shfl_xor_sync(0xffffffffu, tmn, o));
        tmx = fmaxf(tmx, __shfl_xor_sync(0xffffffffu, tmx, o));
    }
    __shared__ float rmn[8], rmx[8];
    if ((tid & 31) == 0) { rmn[tid >> 5] = tmn; rmx[tid >> 5] = tmx; }
    __syncthreads();
    if (tid == 0) {
        #pragma unroll
        for (int w = 0; w < 8; ++w) { tmn = fminf(tmn, rmn[w]); tmx = fmaxf(tmx, rmx[w]); }
        g_pmin[b*16 + blockIdx.y*4 + blockIdx.x] = tmn;
        g_pmax[b*16 + blockIdx.y*4 + blockIdx.x] = tmx;
    }
}

// ---------------------------------------------------------------------------
// 4) Main dynamic conv, per-pixel r selection computed inline.
//    Block: one batch, 32x8 pixel tile. 512 threads: (co-half, ty, tx).
//    Thread: 1 pixel, 32 couts as 16 packed f32x2 accumulators (32 regs).
//    Weights staged in smem for BOTH r -> warp-broadcast reads.
//    fma.rn.f32x2 => 2x fp32 FMA throughput, exact fp32 math.
// ---------------------------------------------------------------------------
#define CTX 32
#define CTY 8

__global__ __launch_bounds__(512, 2)
void conv_main_kernel(const float* __restrict__ feat,
                      const float* __restrict__ pred,
                      float* __restrict__ out) {
    __shared__ float s_feat[8][CTY + 2][CTX + 2];                // [8][10][34]
    __shared__ __align__(16) float s_w[2][8][9][64];             // 36864 B
    __shared__ float s_mn, s_mx;

    const int tid  = threadIdx.x;
    const int tx   = tid & 31;
    const int ty   = (tid >> 5) & 7;
    const int half = tid >> 8;           // 0/1 -> co range
    const int b  = blockIdx.z;
    const int x0 = blockIdx.x * CTX;
    const int y0 = blockIdx.y * CTY;
    const int y = y0 + ty, x = x0 + tx;

    if (tid == 0) {
        float mn = 3.4e38f, mx = 0.f;
        #pragma unroll
        for (int i = 0; i < 16; ++i) {
            mn = fminf(mn, g_pmin[b*16 + i]);
            mx = fmaxf(mx, g_pmax[b*16 + i]);
        }
        s_mn = mn; s_mx = mx;
    }
    __syncthreads();

    // per-pixel r: guide = [h, 1-h]; argmax -> r=1 iff h < 0.5
    const int pix = b*HW + y*128 + x;
    float sa = (g_sa[pix] - s_mn) / (s_mx - s_mn + 1e-8f);
    float pv = 1.f / (1.f + expf(-pred[pix]));
    const int r = (fmaxf(sa, pv) < 0.5f) ? 1 : 0;

    unsigned long long acc[16];
    #pragma unroll
    for (int i = 0; i < 16; ++i) acc[i] = 0ull;

    const unsigned sw_base =
        (unsigned)__cvta_generic_to_shared(&s_w[0][0][0][0])
        + (unsigned)r * (8*9*64*4) + (unsigned)half * 128;

    for (int cc = 0; cc < 8; ++cc) {
        __syncthreads();   // protect smem reuse from previous chunk
        // --- stage feat chunk (8 ci) with halo + zero padding ---
        const float* fsrc = feat + ((size_t)(b*CIN + cc*8)) * HW;
        for (int i = tid; i < 8*10*34; i += 512) {
            int ci = i / 340, rem = i % 340;
            int ly = rem / 34, lx = rem % 34;
            int gy = y0 - 1 + ly, gx = x0 - 1 + lx;
            float v = 0.f;
            if ((unsigned)gy < 128u && (unsigned)gx < 128u)
                v = fsrc[ci*HW + gy*128 + gx];
            s_feat[ci][ly][lx] = v;
        }
        // --- stage weight chunk for both r (contiguous slabs, float4) ---
        {
            const float4* w0 = (const float4*)(g_kern + ((size_t)(b*2 + 0)*CIN + cc*8)*576);
            const float4* w1 = (const float4*)(g_kern + ((size_t)(b*2 + 1)*CIN + cc*8)*576);
            float4* sd = (float4*)s_w;
            for (int i = tid; i < 1152; i += 512) sd[i]        = w0[i];
            for (int i = tid; i < 1152; i += 512) sd[1152 + i] = w1[i];
        }
        __syncthreads();

        // --- compute: 8 ci x 9 taps x 32 couts (packed pairs) ---
        for (int ci = 0; ci < 8; ++ci) {
            #pragma unroll
            for (int k = 0; k < 9; ++k) {
                const int ky = k / 3, kx = k % 3;
                float f = s_feat[ci][ty + ky][tx + kx];
                unsigned long long fp;
                asm("mov.b64 %0, {%1, %1};" : "=l"(fp) : "f"(f));
                const unsigned wa = sw_base + (unsigned)(ci*9 + k) * 256;
                #pragma unroll
                for (int q = 0; q < 8; ++q) {
                    unsigned long long wlo, whi;
                    asm volatile("ld.shared.v2.b64 {%0, %1}, [%2];"
                                 : "=l"(wlo), "=l"(whi) : "r"(wa + q*16));
                    asm("fma.rn.f32x2 %0, %1, %2, %0;" : "+l"(acc[2*q])   : "l"(fp), "l"(wlo));
                    asm("fma.rn.f32x2 %0, %1, %2, %0;" : "+l"(acc[2*q+1]) : "l"(fp), "l"(whi));
                }
            }
        }
    }

    // --- epilogue: unpack and write (coalesced across warp lanes) ---
    float* op = out + ((size_t)b*COUT + half*32)*HW + y*128 + x;
    #pragma unroll
    for (int j = 0; j < 16; ++j) {
        float lo, hi;
        asm("mov.b64 {%0, %1}, %2;" : "=f"(lo), "=f"(hi) : "l"(acc[j]));
        const int co = (j >> 1)*4 + (j & 1)*2;
        op[(size_t)co       * HW] = lo;
        op[(size_t)(co + 1) * HW] = hi;
    }
}

// ---------------------------------------------------------------------------
// Launch: inputs in metadata order: feat, pred, w1, b1, w2, b2, gk
// 4 launches: pool(0), kerngen(1), sa(2), conv(3)
// ---------------------------------------------------------------------------
extern "C" void kernel_launch(void* const* d_in, const int* in_sizes, int n_in,
                              void* d_out, int out_size) {
    const float* feat = (const float*)d_in[0];
    const float* pred = (const float*)d_in[1];
    const float* w1   = (const float*)d_in[2];
    const float* b1   = (const float*)d_in[3];
    const float* w2   = (const float*)d_in[4];
    const float* b2   = (const float*)d_in[5];
    const float* gk   = (const float*)d_in[6];
    float* out = (float*)d_out;

    pool_kernel<<<BB*CIN, 128>>>(feat);
    kerngen_kernel<<<BB*RR*9, 256>>>(w1, b1, w2, b2);

    dim3 gsa(4, 4, BB);
    sa_kernel<<<gsa, 256>>>(pred, gk);

    dim3 gc(WW/CTX, HH/CTY, BB);
    conv_main_kernel<<<gc, 512>>>(feat, pred, out);
}

// round 3
// speedup vs baseline: 1.4673x; 1.4673x over previous
#include <cuda_runtime.h>
#include <math.h>

// ---------------------------------------------------------------------------
// B=8, CIN=64, COUT=64, H=W=128, R=2, HID=8, K=3, GK=15
// ---------------------------------------------------------------------------
#define BB   8
#define CIN  64
#define COUT 64
#define HH   128
#define WW   128
#define RR   2
#define HID  8
#define HW   (HH*WW)          // 16384

// ---------------------------------------------------------------------------
// Device scratch (no allocation allowed)
// ---------------------------------------------------------------------------
__device__ float g_pooled[BB*CIN*9];                 // [b][ci][yx]
// conv weights, layout [b][r][ci][kyx(9)][co]  (co fastest -> packed pairs)
__device__ float g_kern[(size_t)BB*RR*CIN*9*COUT];   // 589824 floats
__device__ float g_sa[BB*HW];
__device__ float g_pmin[BB*16];                      // per-tile sa min partials
__device__ float g_pmax[BB*16];

// ---------------------------------------------------------------------------
// 1) Adaptive avg pool 128x128 -> 3x3 (PyTorch bins: [0,43) [42,86) [85,128))
// ---------------------------------------------------------------------------
__global__ void pool_kernel(const float* __restrict__ feat) {
    const int bc = blockIdx.x;                 // b*64+ci
    const float* src = feat + (size_t)bc * HW;
    float a[9];
    #pragma unroll
    for (int i = 0; i < 9; ++i) a[i] = 0.f;

    for (int idx = threadIdx.x; idx < HW; idx += 128) {
        float v = src[idx];
        int y = idx >> 7, x = idx & 127;
        bool rm0 = (y < 43), rm1 = (y >= 42) & (y < 86), rm2 = (y >= 85);
        bool cm0 = (x < 43), cm1 = (x >= 42) & (x < 86), cm2 = (x >= 85);
        if (rm0) { if (cm0) a[0]+=v; if (cm1) a[1]+=v; if (cm2) a[2]+=v; }
        if (rm1) { if (cm0) a[3]+=v; if (cm1) a[4]+=v; if (cm2) a[5]+=v; }
        if (rm2) { if (cm0) a[6]+=v; if (cm1) a[7]+=v; if (cm2) a[8]+=v; }
    }

    __shared__ float red[9][128];
    #pragma unroll
    for (int k = 0; k < 9; ++k) red[k][threadIdx.x] = a[k];
    __syncthreads();
    for (int s = 64; s > 0; s >>= 1) {
        if (threadIdx.x < s) {
            #pragma unroll
            for (int k = 0; k < 9; ++k)
                red[k][threadIdx.x] += red[k][threadIdx.x + s];
        }
        __syncthreads();
    }
    if (threadIdx.x < 9) {
        const float cnt[3] = {43.f, 44.f, 43.f};
        int i = threadIdx.x / 3, j = threadIdx.x % 3;
        g_pooled[bc*9 + threadIdx.x] = red[threadIdx.x][0] / (cnt[i] * cnt[j]);
    }
}

// ---------------------------------------------------------------------------
// 2) Fused MLP1 + kernel generation.  Block = (b, r, yx), 144 blocks.
// ---------------------------------------------------------------------------
__global__ void kerngen_kernel(const float* __restrict__ w1,
                               const float* __restrict__ b1,
                               const float* __restrict__ w2,
                               const float* __restrict__ b2) {
    const int blk = blockIdx.x;               // 0..143
    const int b = blk / 18, rem = blk % 18;
    const int r = rem / 9, yx = rem % 9;

    __shared__ float hs[8];
    if (threadIdx.x < 8) {
        const int c = r*8 + threadIdx.x;
        float v = b1[c];
        #pragma unroll 8
        for (int ci = 0; ci < CIN; ++ci)
            v += w1[c*CIN + ci] * g_pooled[(b*CIN + ci)*9 + yx];
        hs[threadIdx.x] = 1.f / (1.f + expf(-v));
    }
    __syncthreads();

    for (int idx = threadIdx.x; idx < CIN*COUT; idx += 256) {
        const int co = idx & 63, ci = idx >> 6;
        const int q = r*(CIN*COUT) + co*CIN + ci;
        const float* wp = w2 + (size_t)q * HID;
        float v = b2[q];
        #pragma unroll
        for (int h = 0; h < HID; ++h) v += wp[h] * hs[h];
        g_kern[((size_t)(b*2 + r)*CIN + ci)*576 + yx*64 + co] = v;
    }
}

// ---------------------------------------------------------------------------
// 3) Guide: sigmoid(pred) -> 15x15 gaussian conv -> per-tile min/max partials
// ---------------------------------------------------------------------------
__global__ __launch_bounds__(256) void sa_kernel(const float* __restrict__ pred,
                                                 const float* __restrict__ gk) {
    __shared__ float sp[46][46];
    __shared__ float sg[225];
    const int b  = blockIdx.z;
    const int x0 = blockIdx.x * 32, y0 = blockIdx.y * 32;
    const int tid = threadIdx.x;

    for (int i = tid; i < 225; i += 256) sg[i] = gk[i];
    for (int i = tid; i < 46*46; i += 256) {
        int ly = i / 46, lx = i % 46;
        int gy = y0 - 7 + ly, gx = x0 - 7 + lx;
        float v = 0.f;
        if ((unsigned)gy < 128u && (unsigned)gx < 128u) {
            float pv = pred[b*HW + gy*128 + gx];
            v = 1.f / (1.f + expf(-pv));
        }
        sp[ly][lx] = v;
    }
    __syncthreads();

    float tmn = 3.4e38f, tmx = 0.f;   // sa >= 0
    #pragma unroll
    for (int p = 0; p < 4; ++p) {
        int id = tid + p*256;
        int py = id >> 5, px = id & 31;
        float s = 0.f;
        for (int u = 0; u < 15; ++u) {
            #pragma unroll
            for (int v = 0; v < 15; ++v)
                s += sp[py + u][px + v] * sg[u*15 + v];
        }
        g_sa[b*HW + (y0 + py)*128 + (x0 + px)] = s;
        tmn = fminf(tmn, s); tmx = fmaxf(tmx, s);
    }
    #pragma unroll
    for (int o = 16; o; o >>= 1) {
        tmn = fminf(tmn, __shfl_xor_sync(0xffffffffu, tmn, o));
        tmx = fmaxf(tmx, __shfl_xor_sync(0xffffffffu, tmx, o));
    }
    __shared__ float rmn[8], rmx[8];
    if ((tid & 31) == 0) { rmn[tid >> 5] = tmn; rmx[tid >> 5] = tmx; }
    __syncthreads();
    if (tid == 0) {
        #pragma unroll
        for (int w = 0; w < 8; ++w) { tmn = fminf(tmn, rmn[w]); tmx = fmaxf(tmx, rmx[w]); }
        g_pmin[b*16 + blockIdx.y*4 + blockIdx.x] = tmn;
        g_pmax[b*16 + blockIdx.y*4 + blockIdx.x] = tmx;
    }
}

// ---------------------------------------------------------------------------
// 4) Main dynamic conv with in-block r-compaction.
//    Block: 256 threads, 16x16 pixel tile, one batch.
//    Pixels permuted so r=0 pixels come first; thread = 4 consecutive
//    compacted pixels x 16 couts -> weight LDS amortized 4x.
//    fma.rn.f32x2 packed pairs => exact fp32, 2x FMA throughput.
// ---------------------------------------------------------------------------
#define R_STRIDE_B 18432u   /* 8*9*64 floats * 4B : r slab stride in s_w */

__global__ __launch_bounds__(256, 2)
void conv_main_kernel(const float* __restrict__ feat,
                      const float* __restrict__ pred,
                      float* __restrict__ out) {
    __shared__ float s_feat[8][18][18];                   // 10368 B
    __shared__ __align__(16) float s_w[2][8][9][64];      // 36864 B
    __shared__ int s_cnt[8];
    __shared__ __align__(4) unsigned char s_perm[256];

    const int tid = threadIdx.x;
    const int b  = blockIdx.z;
    const int x0 = blockIdx.x * 16;
    const int y0 = blockIdx.y * 16;

    // ---- per-image sa min/max (16 partials, L2-broadcast) ----
    float mn = 3.4e38f, mx = 0.f;
    #pragma unroll
    for (int i = 0; i < 16; ++i) {
        mn = fminf(mn, g_pmin[b*16 + i]);
        mx = fmaxf(mx, g_pmax[b*16 + i]);
    }

    // ---- compute r for tile pixel `tid`, build compaction permutation ----
    int n0;
    {
        int py = tid >> 4, px = tid & 15;
        int pix = b*HW + (y0 + py)*128 + (x0 + px);
        float sa = (g_sa[pix] - mn) / (mx - mn + 1e-8f);
        float pv = 1.f / (1.f + expf(-pred[pix]));
        int r = (fmaxf(sa, pv) < 0.5f) ? 1 : 0;   // argmax([h,1-h])
        unsigned bal = __ballot_sync(0xffffffffu, r);
        int w = tid >> 5, lane = tid & 31;
        if (lane == 0) s_cnt[w] = __popc(bal);
        __syncthreads();
        int n1 = 0, pre1 = 0;
        #pragma unroll
        for (int i = 0; i < 8; ++i) { int c = s_cnt[i]; n1 += c; if (i < w) pre1 += c; }
        n0 = 256 - n1;
        unsigned lt = (1u << lane) - 1u;
        int pos = r ? (n0 + pre1 + __popc(bal & lt))
                    : ((w*32 - pre1) + __popc(~bal & lt));
        s_perm[pos] = (unsigned char)tid;
        __syncthreads();
    }

    // ---- my 4 compacted pixels, 16 couts ----
    const int p   = tid & 63;
    const int cog = tid >> 6;
    uchar4 ids = *(const uchar4*)&s_perm[p*4];
    const int yA = ids.x >> 4, xA = ids.x & 15;
    const int yB = ids.y >> 4, xB = ids.y & 15;
    const int yC = ids.z >> 4, xC = ids.z & 15;
    const int yD = ids.w >> 4, xD = ids.w & 15;
    const float* fbA = &s_feat[0][yA][xA];
    const float* fbB = &s_feat[0][yB][xB];
    const float* fbC = &s_feat[0][yC][xC];
    const float* fbD = &s_feat[0][yD][xD];
    const int rA = (4*p + 0 >= n0);
    const int rD = (4*p + 3 >= n0);
    const bool uniform = (rA == rD);

    const unsigned swb = (unsigned)__cvta_generic_to_shared(&s_w[0][0][0][0])
                       + (unsigned)cog * 64u;
    const unsigned wbU = swb + (unsigned)rA * R_STRIDE_B;
    const unsigned wb0 = swb + (unsigned)rA * R_STRIDE_B;
    const unsigned wb1 = swb + (unsigned)((4*p + 1 >= n0) ? 1u : 0u) * R_STRIDE_B;
    const unsigned wb2 = swb + (unsigned)((4*p + 2 >= n0) ? 1u : 0u) * R_STRIDE_B;
    const unsigned wb3 = swb + (unsigned)rD * R_STRIDE_B;

    unsigned long long acc[4][8];
    #pragma unroll
    for (int i = 0; i < 4; ++i)
        #pragma unroll
        for (int j = 0; j < 8; ++j) acc[i][j] = 0ull;

    for (int cc = 0; cc < 8; ++cc) {
        __syncthreads();   // protect smem reuse
        // --- stage feat chunk (8 ci) with halo + zero padding ---
        const float* fsrc = feat + ((size_t)(b*CIN + cc*8)) * HW;
        for (int i = tid; i < 8*18*18; i += 256) {
            int ci = i / 324, rem = i - ci*324;
            int ly = rem / 18, lx = rem - ly*18;
            int gy = y0 - 1 + ly, gx = x0 - 1 + lx;
            float v = 0.f;
            if ((unsigned)gy < 128u && (unsigned)gx < 128u)
                v = fsrc[ci*HW + gy*128 + gx];
            s_feat[ci][ly][lx] = v;
        }
        // --- stage weights for both r ---
        {
            const float4* w0 = (const float4*)(g_kern + ((size_t)(b*2 + 0)*CIN + cc*8)*576);
            const float4* w1 = (const float4*)(g_kern + ((size_t)(b*2 + 1)*CIN + cc*8)*576);
            float4* sd = (float4*)s_w;
            for (int i = tid; i < 2304; i += 256)
                sd[i] = (i < 1152) ? w0[i] : w1[i - 1152];
        }
        __syncthreads();

        if (uniform) {
            #pragma unroll 1
            for (int ci = 0; ci < 8; ++ci) {
                #pragma unroll
                for (int k = 0; k < 9; ++k) {
                    const int ky = k / 3, kx = k - ky*3;
                    const int fo = ci*324 + ky*18 + kx;
                    float fA = fbA[fo], fB = fbB[fo], fC = fbC[fo], fD = fbD[fo];
                    unsigned long long pA, pB, pC, pD;
                    asm("mov.b64 %0, {%1, %1};" : "=l"(pA) : "f"(fA));
                    asm("mov.b64 %0, {%1, %1};" : "=l"(pB) : "f"(fB));
                    asm("mov.b64 %0, {%1, %1};" : "=l"(pC) : "f"(fC));
                    asm("mov.b64 %0, {%1, %1};" : "=l"(pD) : "f"(fD));
                    const unsigned wa = wbU + (unsigned)(ci*9 + k) * 256u;
                    unsigned long long w_[8];
                    asm volatile("ld.shared.v2.b64 {%0,%1},[%2];"    : "=l"(w_[0]), "=l"(w_[1]) : "r"(wa));
                    asm volatile("ld.shared.v2.b64 {%0,%1},[%2+16];" : "=l"(w_[2]), "=l"(w_[3]) : "r"(wa));
                    asm volatile("ld.shared.v2.b64 {%0,%1},[%2+32];" : "=l"(w_[4]), "=l"(w_[5]) : "r"(wa));
                    asm volatile("ld.shared.v2.b64 {%0,%1},[%2+48];" : "=l"(w_[6]), "=l"(w_[7]) : "r"(wa));
                    #pragma unroll
                    for (int q = 0; q < 8; ++q) {
                        asm("fma.rn.f32x2 %0,%1,%2,%0;" : "+l"(acc[0][q]) : "l"(pA), "l"(w_[q]));
                        asm("fma.rn.f32x2 %0,%1,%2,%0;" : "+l"(acc[1][q]) : "l"(pB), "l"(w_[q]));
                        asm("fma.rn.f32x2 %0,%1,%2,%0;" : "+l"(acc[2][q]) : "l"(pC), "l"(w_[q]));
                        asm("fma.rn.f32x2 %0,%1,%2,%0;" : "+l"(acc[3][q]) : "l"(pD), "l"(w_[q]));
                    }
                }
            }
        } else {
            // rare boundary thread: per-pixel r
            #pragma unroll 1
            for (int ci = 0; ci < 8; ++ci) {
                #pragma unroll
                for (int k = 0; k < 9; ++k) {
                    const int ky = k / 3, kx = k - ky*3;
                    const int fo = ci*324 + ky*18 + kx;
                    const unsigned ko = (unsigned)(ci*9 + k) * 256u;
                    const float fv[4] = {fbA[fo], fbB[fo], fbC[fo], fbD[fo]};
                    const unsigned wb[4] = {wb0 + ko, wb1 + ko, wb2 + ko, wb3 + ko};
                    #pragma unroll
                    for (int i2 = 0; i2 < 4; ++i2) {
                        unsigned long long fp;
                        asm("mov.b64 %0, {%1, %1};" : "=l"(fp) : "f"(fv[i2]));
                        unsigned long long w_[8];
                        asm volatile("ld.shared.v2.b64 {%0,%1},[%2];"    : "=l"(w_[0]), "=l"(w_[1]) : "r"(wb[i2]));
                        asm volatile("ld.shared.v2.b64 {%0,%1},[%2+16];" : "=l"(w_[2]), "=l"(w_[3]) : "r"(wb[i2]));
                        asm volatile("ld.shared.v2.b64 {%0,%1},[%2+32];" : "=l"(w_[4]), "=l"(w_[5]) : "r"(wb[i2]));
                        asm volatile("ld.shared.v2.b64 {%0,%1},[%2+48];" : "=l"(w_[6]), "=l"(w_[7]) : "r"(wb[i2]));
                        #pragma unroll
                        for (int q = 0; q < 8; ++q)
                            asm("fma.rn.f32x2 %0,%1,%2,%0;" : "+l"(acc[i2][q]) : "l"(fp), "l"(w_[q]));
                    }
                }
            }
        }
    }

    // ---- epilogue: scatter 4 pixels x 16 couts ----
    const int poff[4] = {(y0+yA)*128 + x0+xA, (y0+yB)*128 + x0+xB,
                         (y0+yC)*128 + x0+xC, (y0+yD)*128 + x0+xD};
    #pragma unroll
    for (int j = 0; j < 8; ++j) {
        const int co = cog*16 + 2*j;
        float* o0 = out + ((size_t)(b*COUT + co)) * HW;
        #pragma unroll
        for (int i2 = 0; i2 < 4; ++i2) {
            float lo, hi;
            asm("mov.b64 {%0,%1},%2;" : "=f"(lo), "=f"(hi) : "l"(acc[i2][j]));
            o0[poff[i2]]      = lo;
            o0[poff[i2] + HW] = hi;
        }
    }
}

// ---------------------------------------------------------------------------
// Launch: inputs in metadata order: feat, pred, w1, b1, w2, b2, gk
// ---------------------------------------------------------------------------
extern "C" void kernel_launch(void* const* d_in, const int* in_sizes, int n_in,
                              void* d_out, int out_size) {
    const float* feat = (const float*)d_in[0];
    const float* pred = (const float*)d_in[1];
    const float* w1   = (const float*)d_in[2];
    const float* b1   = (const float*)d_in[3];
    const float* w2   = (const float*)d_in[4];
    const float* b2   = (const float*)d_in[5];
    const float* gk   = (const float*)d_in[6];
    float* out = (float*)d_out;

    pool_kernel<<<BB*CIN, 128>>>(feat);
    kerngen_kernel<<<BB*RR*9, 256>>>(w1, b1, w2, b2);

    dim3 gsa(4, 4, BB);
    sa_kernel<<<gsa, 256>>>(pred, gk);

    dim3 gc(8, 8, BB);
    conv_main_kernel<<<gc, 256>>>(feat, pred, out);
}

// round 4
// speedup vs baseline: 1.5224x; 1.0375x over previous
#include <cuda_runtime.h>
#include <math.h>

// ---------------------------------------------------------------------------
// B=8, CIN=64, COUT=64, H=W=128, R=2, HID=8, K=3, GK=15
// ---------------------------------------------------------------------------
#define BB   8
#define CIN  64
#define COUT 64
#define HH   128
#define WW   128
#define RR   2
#define HID  8
#define HW   (HH*WW)          // 16384

// ---------------------------------------------------------------------------
// Device scratch (no allocation allowed)
// ---------------------------------------------------------------------------
__device__ float g_pooled[BB*CIN*9];                 // [b][ci][yx]
// conv weights, layout [b][r][ci][kyx(9)][co]  (co fastest -> packed pairs)
__device__ float g_kern[(size_t)BB*RR*CIN*9*COUT];   // 589824 floats
__device__ float g_sa[BB*HW];
__device__ float g_pmin[BB*16];                      // per-tile sa min partials
__device__ float g_pmax[BB*16];

// ---------------------------------------------------------------------------
// 1) Adaptive avg pool 128x128 -> 3x3 (PyTorch bins: [0,43) [42,86) [85,128))
// ---------------------------------------------------------------------------
__global__ void pool_kernel(const float* __restrict__ feat) {
    const int bc = blockIdx.x;                 // b*64+ci
    const float* src = feat + (size_t)bc * HW;
    float a[9];
    #pragma unroll
    for (int i = 0; i < 9; ++i) a[i] = 0.f;

    for (int idx = threadIdx.x; idx < HW; idx += 128) {
        float v = src[idx];
        int y = idx >> 7, x = idx & 127;
        bool rm0 = (y < 43), rm1 = (y >= 42) & (y < 86), rm2 = (y >= 85);
        bool cm0 = (x < 43), cm1 = (x >= 42) & (x < 86), cm2 = (x >= 85);
        if (rm0) { if (cm0) a[0]+=v; if (cm1) a[1]+=v; if (cm2) a[2]+=v; }
        if (rm1) { if (cm0) a[3]+=v; if (cm1) a[4]+=v; if (cm2) a[5]+=v; }
        if (rm2) { if (cm0) a[6]+=v; if (cm1) a[7]+=v; if (cm2) a[8]+=v; }
    }

    __shared__ float red[9][128];
    #pragma unroll
    for (int k = 0; k < 9; ++k) red[k][threadIdx.x] = a[k];
    __syncthreads();
    for (int s = 64; s > 0; s >>= 1) {
        if (threadIdx.x < s) {
            #pragma unroll
            for (int k = 0; k < 9; ++k)
                red[k][threadIdx.x] += red[k][threadIdx.x + s];
        }
        __syncthreads();
    }
    if (threadIdx.x < 9) {
        const float cnt[3] = {43.f, 44.f, 43.f};
        int i = threadIdx.x / 3, j = threadIdx.x % 3;
        g_pooled[bc*9 + threadIdx.x] = red[threadIdx.x][0] / (cnt[i] * cnt[j]);
    }
}

// ---------------------------------------------------------------------------
// 2) Fused MLP1 + kernel generation.  Block = (b, r, yx), 144 blocks.
// ---------------------------------------------------------------------------
__global__ void kerngen_kernel(const float* __restrict__ w1,
                               const float* __restrict__ b1,
                               const float* __restrict__ w2,
                               const float* __restrict__ b2) {
    const int blk = blockIdx.x;               // 0..143
    const int b = blk / 18, rem = blk % 18;
    const int r = rem / 9, yx = rem % 9;

    __shared__ float hs[8];
    if (threadIdx.x < 8) {
        const int c = r*8 + threadIdx.x;
        float v = b1[c];
        #pragma unroll 8
        for (int ci = 0; ci < CIN; ++ci)
            v += w1[c*CIN + ci] * g_pooled[(b*CIN + ci)*9 + yx];
        hs[threadIdx.x] = 1.f / (1.f + expf(-v));
    }
    __syncthreads();

    for (int idx = threadIdx.x; idx < CIN*COUT; idx += 256) {
        const int co = idx & 63, ci = idx >> 6;
        const int q = r*(CIN*COUT) + co*CIN + ci;
        const float* wp = w2 + (size_t)q * HID;
        float v = b2[q];
        #pragma unroll
        for (int h = 0; h < HID; ++h) v += wp[h] * hs[h];
        g_kern[((size_t)(b*2 + r)*CIN + ci)*576 + yx*64 + co] = v;
    }
}

// ---------------------------------------------------------------------------
// 3) Guide: sigmoid(pred) -> 15x15 gaussian conv -> per-tile min/max partials
// ---------------------------------------------------------------------------
__global__ __launch_bounds__(256) void sa_kernel(const float* __restrict__ pred,
                                                 const float* __restrict__ gk) {
    __shared__ float sp[46][46];
    __shared__ float sg[225];
    const int b  = blockIdx.z;
    const int x0 = blockIdx.x * 32, y0 = blockIdx.y * 32;
    const int tid = threadIdx.x;

    for (int i = tid; i < 225; i += 256) sg[i] = gk[i];
    for (int i = tid; i < 46*46; i += 256) {
        int ly = i / 46, lx = i % 46;
        int gy = y0 - 7 + ly, gx = x0 - 7 + lx;
        float v = 0.f;
        if ((unsigned)gy < 128u && (unsigned)gx < 128u) {
            float pv = pred[b*HW + gy*128 + gx];
            v = 1.f / (1.f + expf(-pv));
        }
        sp[ly][lx] = v;
    }
    __syncthreads();

    float tmn = 3.4e38f, tmx = 0.f;   // sa >= 0
    #pragma unroll
    for (int p = 0; p < 4; ++p) {
        int id = tid + p*256;
        int py = id >> 5, px = id & 31;
        float s = 0.f;
        for (int u = 0; u < 15; ++u) {
            #pragma unroll
            for (int v = 0; v < 15; ++v)
                s += sp[py + u][px + v] * sg[u*15 + v];
        }
        g_sa[b*HW + (y0 + py)*128 + (x0 + px)] = s;
        tmn = fminf(tmn, s); tmx = fmaxf(tmx, s);
    }
    #pragma unroll
    for (int o = 16; o; o >>= 1) {
        tmn = fminf(tmn, __shfl_xor_sync(0xffffffffu, tmn, o));
        tmx = fmaxf(tmx, __shfl_xor_sync(0xffffffffu, tmx, o));
    }
    __shared__ float rmn[8], rmx[8];
    if ((tid & 31) == 0) { rmn[tid >> 5] = tmn; rmx[tid >> 5] = tmx; }
    __syncthreads();
    if (tid == 0) {
        #pragma unroll
        for (int w = 0; w < 8; ++w) { tmn = fminf(tmn, rmn[w]); tmx = fmaxf(tmx, rmx[w]); }
        g_pmin[b*16 + blockIdx.y*4 + blockIdx.x] = tmn;
        g_pmax[b*16 + blockIdx.y*4 + blockIdx.x] = tmx;
    }
}

// ---------------------------------------------------------------------------
// 4) Main dynamic conv with bank-aware r-compaction.
//    Counting sort by key = r*32 + smem_bank(pixel): r=0 first (r uniform
//    per thread except one straddler), and each thread's 4 consecutive
//    slots share one bank while warp lanes spread across banks
//    -> feat LDS ~conflict-free. fma.rn.f32x2 packed pairs (exact fp32).
// ---------------------------------------------------------------------------
#define R_STRIDE_B 18432u   /* 8*9*64 floats * 4B : r slab stride in s_w */

__global__ __launch_bounds__(256, 2)
void conv_main_kernel(const float* __restrict__ feat,
                      const float* __restrict__ pred,
                      float* __restrict__ out) {
    __shared__ float s_feat[8][18][18];                   // 10368 B
    __shared__ __align__(16) float s_w[2][8][9][64];      // 36864 B
    __shared__ int s_bucket[64];
    __shared__ int s_prefix[65];
    __shared__ __align__(4) unsigned char s_perm[256];

    const int tid = threadIdx.x;
    const int b  = blockIdx.z;
    const int x0 = blockIdx.x * 16;
    const int y0 = blockIdx.y * 16;

    // ---- per-image sa min/max (16 partials, L2-broadcast) ----
    float mn = 3.4e38f, mx = 0.f;
    #pragma unroll
    for (int i = 0; i < 16; ++i) {
        mn = fminf(mn, g_pmin[b*16 + i]);
        mx = fmaxf(mx, g_pmax[b*16 + i]);
    }

    // ---- r per pixel + bank-aware counting sort ----
    if (tid < 64) s_bucket[tid] = 0;
    __syncthreads();
    int key, rank;
    {
        int py = tid >> 4, px = tid & 15;
        int pix = b*HW + (y0 + py)*128 + (x0 + px);
        float sa = (g_sa[pix] - mn) / (mx - mn + 1e-8f);
        float pv = 1.f / (1.f + expf(-pred[pix]));
        int r = (fmaxf(sa, pv) < 0.5f) ? 1 : 0;   // argmax([h,1-h])
        int bank = (py*18 + px) & 31;             // smem bank of this pixel
        key = r*32 + bank;
        rank = atomicAdd(&s_bucket[key], 1);
    }
    __syncthreads();
    if (tid == 0) {
        int a = 0;
        #pragma unroll 8
        for (int i = 0; i < 64; ++i) { s_prefix[i] = a; a += s_bucket[i]; }
        s_prefix[64] = a;
    }
    __syncthreads();
    s_perm[s_prefix[key] + rank] = (unsigned char)tid;
    const int n0 = s_prefix[32];
    __syncthreads();

    // ---- my 4 compacted pixels, 16 couts ----
    const int p   = tid & 63;
    const int cog = tid >> 6;
    uchar4 ids = *(const uchar4*)&s_perm[p*4];
    const int yA = ids.x >> 4, xA = ids.x & 15;
    const int yB = ids.y >> 4, xB = ids.y & 15;
    const int yC = ids.z >> 4, xC = ids.z & 15;
    const int yD = ids.w >> 4, xD = ids.w & 15;
    const float* fbA = &s_feat[0][yA][xA];
    const float* fbB = &s_feat[0][yB][xB];
    const float* fbC = &s_feat[0][yC][xC];
    const float* fbD = &s_feat[0][yD][xD];
    const int rA = (4*p + 0 >= n0);
    const int rD = (4*p + 3 >= n0);
    const bool uniform = (rA == rD);

    const unsigned swb = (unsigned)__cvta_generic_to_shared(&s_w[0][0][0][0])
                       + (unsigned)cog * 64u;
    const unsigned wbU = swb + (unsigned)rA * R_STRIDE_B;
    const unsigned wb0 = swb + (unsigned)rA * R_STRIDE_B;
    const unsigned wb1 = swb + (unsigned)((4*p + 1 >= n0) ? 1u : 0u) * R_STRIDE_B;
    const unsigned wb2 = swb + (unsigned)((4*p + 2 >= n0) ? 1u : 0u) * R_STRIDE_B;
    const unsigned wb3 = swb + (unsigned)rD * R_STRIDE_B;

    unsigned long long acc[4][8];
    #pragma unroll
    for (int i = 0; i < 4; ++i)
        #pragma unroll
        for (int j = 0; j < 8; ++j) acc[i][j] = 0ull;

    for (int cc = 0; cc < 8; ++cc) {
        __syncthreads();   // protect smem reuse
        // --- stage feat chunk (8 ci) with halo + zero padding ---
        const float* fsrc = feat + ((size_t)(b*CIN + cc*8)) * HW;
        for (int i = tid; i < 8*18*18; i += 256) {
            int ci = i / 324, rem = i - ci*324;
            int ly = rem / 18, lx = rem - ly*18;
            int gy = y0 - 1 + ly, gx = x0 - 1 + lx;
            float v = 0.f;
            if ((unsigned)gy < 128u && (unsigned)gx < 128u)
                v = fsrc[ci*HW + gy*128 + gx];
            s_feat[ci][ly][lx] = v;
        }
        // --- stage weights for both r ---
        {
            const float4* w0 = (const float4*)(g_kern + ((size_t)(b*2 + 0)*CIN + cc*8)*576);
            const float4* w1 = (const float4*)(g_kern + ((size_t)(b*2 + 1)*CIN + cc*8)*576);
            float4* sd = (float4*)s_w;
            for (int i = tid; i < 1152; i += 256) sd[i]        = w0[i];
            for (int i = tid; i < 1152; i += 256) sd[1152 + i] = w1[i];
        }
        __syncthreads();

        if (uniform) {
            #pragma unroll 1
            for (int ci = 0; ci < 8; ++ci) {
                #pragma unroll
                for (int k = 0; k < 9; ++k) {
                    const int ky = k / 3, kx = k - ky*3;
                    const int fo = ci*324 + ky*18 + kx;
                    float fA = fbA[fo], fB = fbB[fo], fC = fbC[fo], fD = fbD[fo];
                    unsigned long long pA, pB, pC, pD;
                    asm("mov.b64 %0, {%1, %1};" : "=l"(pA) : "f"(fA));
                    asm("mov.b64 %0, {%1, %1};" : "=l"(pB) : "f"(fB));
                    asm("mov.b64 %0, {%1, %1};" : "=l"(pC) : "f"(fC));
                    asm("mov.b64 %0, {%1, %1};" : "=l"(pD) : "f"(fD));
                    const unsigned wa = wbU + (unsigned)(ci*9 + k) * 256u;
                    unsigned long long w_[8];
                    asm volatile("ld.shared.v2.b64 {%0,%1},[%2];"    : "=l"(w_[0]), "=l"(w_[1]) : "r"(wa));
                    asm volatile("ld.shared.v2.b64 {%0,%1},[%2+16];" : "=l"(w_[2]), "=l"(w_[3]) : "r"(wa));
                    asm volatile("ld.shared.v2.b64 {%0,%1},[%2+32];" : "=l"(w_[4]), "=l"(w_[5]) : "r"(wa));
                    asm volatile("ld.shared.v2.b64 {%0,%1},[%2+48];" : "=l"(w_[6]), "=l"(w_[7]) : "r"(wa));
                    #pragma unroll
                    for (int q = 0; q < 8; ++q) {
                        asm("fma.rn.f32x2 %0,%1,%2,%0;" : "+l"(acc[0][q]) : "l"(pA), "l"(w_[q]));
                        asm("fma.rn.f32x2 %0,%1,%2,%0;" : "+l"(acc[1][q]) : "l"(pB), "l"(w_[q]));
                        asm("fma.rn.f32x2 %0,%1,%2,%0;" : "+l"(acc[2][q]) : "l"(pC), "l"(w_[q]));
                        asm("fma.rn.f32x2 %0,%1,%2,%0;" : "+l"(acc[3][q]) : "l"(pD), "l"(w_[q]));
                    }
                }
            }
        } else {
            // rare boundary thread: per-pixel r
            #pragma unroll 1
            for (int ci = 0; ci < 8; ++ci) {
                #pragma unroll
                for (int k = 0; k < 9; ++k) {
                    const int ky = k / 3, kx = k - ky*3;
                    const int fo = ci*324 + ky*18 + kx;
                    const unsigned ko = (unsigned)(ci*9 + k) * 256u;
                    const float fv[4] = {fbA[fo], fbB[fo], fbC[fo], fbD[fo]};
                    const unsigned wb[4] = {wb0 + ko, wb1 + ko, wb2 + ko, wb3 + ko};
                    #pragma unroll
                    for (int i2 = 0; i2 < 4; ++i2) {
                        unsigned long long fp;
                        asm("mov.b64 %0, {%1, %1};" : "=l"(fp) : "f"(fv[i2]));
                        unsigned long long w_[8];
                        asm volatile("ld.shared.v2.b64 {%0,%1},[%2];"    : "=l"(w_[0]), "=l"(w_[1]) : "r"(wb[i2]));
                        asm volatile("ld.shared.v2.b64 {%0,%1},[%2+16];" : "=l"(w_[2]), "=l"(w_[3]) : "r"(wb[i2]));
                        asm volatile("ld.shared.v2.b64 {%0,%1},[%2+32];" : "=l"(w_[4]), "=l"(w_[5]) : "r"(wb[i2]));
                        asm volatile("ld.shared.v2.b64 {%0,%1},[%2+48];" : "=l"(w_[6]), "=l"(w_[7]) : "r"(wb[i2]));
                        #pragma unroll
                        for (int q = 0; q < 8; ++q)
                            asm("fma.rn.f32x2 %0,%1,%2,%0;" : "+l"(acc[i2][q]) : "l"(fp), "l"(w_[q]));
                    }
                }
            }
        }
    }

    // ---- epilogue: scatter 4 pixels x 16 couts ----
    const int poff[4] = {(y0+yA)*128 + x0+xA, (y0+yB)*128 + x0+xB,
                         (y0+yC)*128 + x0+xC, (y0+yD)*128 + x0+xD};
    #pragma unroll
    for (int j = 0; j < 8; ++j) {
        const int co = cog*16 + 2*j;
        float* o0 = out + ((size_t)(b*COUT + co)) * HW;
        #pragma unroll
        for (int i2 = 0; i2 < 4; ++i2) {
            float lo, hi;
            asm("mov.b64 {%0,%1},%2;" : "=f"(lo), "=f"(hi) : "l"(acc[i2][j]));
            o0[poff[i2]]      = lo;
            o0[poff[i2] + HW] = hi;
        }
    }
}

// ---------------------------------------------------------------------------
// Launch: inputs in metadata order: feat, pred, w1, b1, w2, b2, gk
// ---------------------------------------------------------------------------
extern "C" void kernel_launch(void* const* d_in, const int* in_sizes, int n_in,
                              void* d_out, int out_size) {
    const float* feat = (const float*)d_in[0];
    const float* pred = (const float*)d_in[1];
    const float* w1   = (const float*)d_in[2];
    const float* b1   = (const float*)d_in[3];
    const float* w2   = (const float*)d_in[4];
    const float* b2   = (const float*)d_in[5];
    const float* gk   = (const float*)d_in[6];
    float* out = (float*)d_out;

    pool_kernel<<<BB*CIN, 128>>>(feat);
    kerngen_kernel<<<BB*RR*9, 256>>>(w1, b1, w2, b2);

    dim3 gsa(4, 4, BB);
    sa_kernel<<<gsa, 256>>>(pred, gk);

    dim3 gc(8, 8, BB);
    conv_main_kernel<<<gc, 256>>>(feat, pred, out);
}

// round 6
// speedup vs baseline: 1.9968x; 1.3116x over previous
#include <cuda_runtime.h>
#include <math.h>

// ---------------------------------------------------------------------------
// B=8, CIN=64, COUT=64, H=W=128, R=2, HID=8, K=3, GK=15
// ---------------------------------------------------------------------------
#define BB   8
#define CIN  64
#define COUT 64
#define HH   128
#define WW   128
#define RR   2
#define HID  8
#define HW   (HH*WW)          // 16384

// ---------------------------------------------------------------------------
// Device scratch (no allocation allowed)
// ---------------------------------------------------------------------------
__device__ float g_pooled[BB*CIN*9];                 // [b][ci][yx]
// conv weights, layout [b][r][ci][kyx(9)][co]  (co fastest -> packed pairs)
__device__ float g_kern[(size_t)BB*RR*CIN*9*COUT];   // 589824 floats
__device__ float g_sa[BB*HW];
__device__ float g_pmin[BB*16];                      // per-tile sa min partials
__device__ float g_pmax[BB*16];

// ---------------------------------------------------------------------------
// 1) Adaptive avg pool 128x128 -> 3x3 (PyTorch bins: [0,43) [42,86) [85,128))
// ---------------------------------------------------------------------------
__global__ void pool_kernel(const float* __restrict__ feat) {
    const int bc = blockIdx.x;                 // b*64+ci
    const float* src = feat + (size_t)bc * HW;
    float a[9];
    #pragma unroll
    for (int i = 0; i < 9; ++i) a[i] = 0.f;

    for (int idx = threadIdx.x; idx < HW; idx += 128) {
        float v = src[idx];
        int y = idx >> 7, x = idx & 127;
        bool rm0 = (y < 43), rm1 = (y >= 42) & (y < 86), rm2 = (y >= 85);
        bool cm0 = (x < 43), cm1 = (x >= 42) & (x < 86), cm2 = (x >= 85);
        if (rm0) { if (cm0) a[0]+=v; if (cm1) a[1]+=v; if (cm2) a[2]+=v; }
        if (rm1) { if (cm0) a[3]+=v; if (cm1) a[4]+=v; if (cm2) a[5]+=v; }
        if (rm2) { if (cm0) a[6]+=v; if (cm1) a[7]+=v; if (cm2) a[8]+=v; }
    }

    __shared__ float red[9][128];
    #pragma unroll
    for (int k = 0; k < 9; ++k) red[k][threadIdx.x] = a[k];
    __syncthreads();
    for (int s = 64; s > 0; s >>= 1) {
        if (threadIdx.x < s) {
            #pragma unroll
            for (int k = 0; k < 9; ++k)
                red[k][threadIdx.x] += red[k][threadIdx.x + s];
        }
        __syncthreads();
    }
    if (threadIdx.x < 9) {
        const float cnt[3] = {43.f, 44.f, 43.f};
        int i = threadIdx.x / 3, j = threadIdx.x % 3;
        g_pooled[bc*9 + threadIdx.x] = red[threadIdx.x][0] / (cnt[i] * cnt[j]);
    }
}

// ---------------------------------------------------------------------------
// 2) Fused MLP1 + kernel generation.  Block = (b, r, yx), 144 blocks.
// ---------------------------------------------------------------------------
__global__ void kerngen_kernel(const float* __restrict__ w1,
                               const float* __restrict__ b1,
                               const float* __restrict__ w2,
                               const float* __restrict__ b2) {
    const int blk = blockIdx.x;               // 0..143
    const int b = blk / 18, rem = blk % 18;
    const int r = rem / 9, yx = rem % 9;

    __shared__ float hs[8];
    if (threadIdx.x < 8) {
        const int c = r*8 + threadIdx.x;
        float v = b1[c];
        #pragma unroll 8
        for (int ci = 0; ci < CIN; ++ci)
            v += w1[c*CIN + ci] * g_pooled[(b*CIN + ci)*9 + yx];
        hs[threadIdx.x] = 1.f / (1.f + expf(-v));
    }
    __syncthreads();

    for (int idx = threadIdx.x; idx < CIN*COUT; idx += 256) {
        const int co = idx & 63, ci = idx >> 6;
        const int q = r*(CIN*COUT) + co*CIN + ci;
        const float* wp = w2 + (size_t)q * HID;
        float v = b2[q];
        #pragma unroll
        for (int h = 0; h < HID; ++h) v += wp[h] * hs[h];
        g_kern[((size_t)(b*2 + r)*CIN + ci)*576 + yx*64 + co] = v;
    }
}

// ---------------------------------------------------------------------------
// 3) Guide: sigmoid(pred) -> 15x15 gaussian conv -> per-tile min/max partials
// ---------------------------------------------------------------------------
__global__ __launch_bounds__(256) void sa_kernel(const float* __restrict__ pred,
                                                 const float* __restrict__ gk) {
    __shared__ float sp[46][46];
    __shared__ float sg[225];
    const int b  = blockIdx.z;
    const int x0 = blockIdx.x * 32, y0 = blockIdx.y * 32;
    const int tid = threadIdx.x;

    for (int i = tid; i < 225; i += 256) sg[i] = gk[i];
    for (int i = tid; i < 46*46; i += 256) {
        int ly = i / 46, lx = i % 46;
        int gy = y0 - 7 + ly, gx = x0 - 7 + lx;
        float v = 0.f;
        if ((unsigned)gy < 128u && (unsigned)gx < 128u) {
            float pv = pred[b*HW + gy*128 + gx];
            v = 1.f / (1.f + expf(-pv));
        }
        sp[ly][lx] = v;
    }
    __syncthreads();

    float tmn = 3.4e38f, tmx = 0.f;   // sa >= 0
    #pragma unroll
    for (int p = 0; p < 4; ++p) {
        int id = tid + p*256;
        int py = id >> 5, px = id & 31;
        float s = 0.f;
        for (int u = 0; u < 15; ++u) {
            #pragma unroll
            for (int v = 0; v < 15; ++v)
                s += sp[py + u][px + v] * sg[u*15 + v];
        }
        g_sa[b*HW + (y0 + py)*128 + (x0 + px)] = s;
        tmn = fminf(tmn, s); tmx = fmaxf(tmx, s);
    }
    #pragma unroll
    for (int o = 16; o; o >>= 1) {
        tmn = fminf(tmn, __shfl_xor_sync(0xffffffffu, tmn, o));
        tmx = fmaxf(tmx, __shfl_xor_sync(0xffffffffu, tmx, o));
    }
    __shared__ float rmn[8], rmx[8];
    if ((tid & 31) == 0) { rmn[tid >> 5] = tmn; rmx[tid >> 5] = tmx; }
    __syncthreads();
    if (tid == 0) {
        #pragma unroll
        for (int w = 0; w < 8; ++w) { tmn = fminf(tmn, rmn[w]); tmx = fmaxf(tmx, rmx[w]); }
        g_pmin[b*16 + blockIdx.y*4 + blockIdx.x] = tmn;
        g_pmax[b*16 + blockIdx.y*4 + blockIdx.x] = tmx;
    }
}

// ---------------------------------------------------------------------------
// 4) Main dynamic conv: bank-sorted r-compaction, branch-free uniform inner
//    loop (straddler pixels fixed up at the end), cp.async double-buffered
//    staging of feat+weights. fma.rn.f32x2 packed pairs (exact fp32).
//
//    Dynamic smem layout:
//      [0      , 20736)  s_feat[2][8][18][18]
//      [20736  , 94464)  s_w  [2][2][8][9][64]   (buf, r, ci, k, co)
// ---------------------------------------------------------------------------
#define FEAT_BUF_B 10368u
#define W_BUF_B    36864u
#define W_R_B      18432u

extern __shared__ __align__(16) char dsm[];

__global__ __launch_bounds__(256, 2)
void conv_main_kernel(const float* __restrict__ feat,
                      const float* __restrict__ pred,
                      float* __restrict__ out) {
    __shared__ int s_bucket[64];
    __shared__ int s_prefix[65];
    __shared__ __align__(4) unsigned char s_perm[256];

    float* s_featp = (float*)dsm;
    const unsigned featsm = (unsigned)__cvta_generic_to_shared(dsm);
    const unsigned wsm    = featsm + 2u*FEAT_BUF_B;

    const int tid = threadIdx.x;
    const int b  = blockIdx.z;
    const int x0 = blockIdx.x * 16;
    const int y0 = blockIdx.y * 16;

    // ---- per-image sa min/max (16 partials, L2-broadcast) ----
    float mn = 3.4e38f, mx = 0.f;
    #pragma unroll
    for (int i = 0; i < 16; ++i) {
        mn = fminf(mn, g_pmin[b*16 + i]);
        mx = fmaxf(mx, g_pmax[b*16 + i]);
    }

    // ---- r per pixel + bank-aware counting sort ----
    if (tid < 64) s_bucket[tid] = 0;
    __syncthreads();
    int key, rank;
    {
        int py = tid >> 4, px = tid & 15;
        int pix = b*HW + (y0 + py)*128 + (x0 + px);
        float sa = (g_sa[pix] - mn) / (mx - mn + 1e-8f);
        float pv = 1.f / (1.f + expf(-pred[pix]));
        int r = (fmaxf(sa, pv) < 0.5f) ? 1 : 0;   // argmax([h,1-h])
        int bank = (py*18 + px) & 31;             // smem bank of this pixel
        key = r*32 + bank;
        rank = atomicAdd(&s_bucket[key], 1);
    }
    __syncthreads();
    if (tid == 0) {
        int a = 0;
        #pragma unroll 8
        for (int i = 0; i < 64; ++i) { s_prefix[i] = a; a += s_bucket[i]; }
        s_prefix[64] = a;
    }
    __syncthreads();
    s_perm[s_prefix[key] + rank] = (unsigned char)tid;
    const int n0 = s_prefix[32];
    __syncthreads();

    // ---- my 4 compacted pixels, 16 couts ----
    const int p   = tid & 63;
    const int cog = tid >> 6;
    uchar4 ids = *(const uchar4*)&s_perm[p*4];
    const int yA = ids.x >> 4, xA = ids.x & 15;
    const int yB = ids.y >> 4, xB = ids.y & 15;
    const int yC = ids.z >> 4, xC = ids.z & 15;
    const int yD = ids.w >> 4, xD = ids.w & 15;
    const float* fbA = s_featp + yA*18 + xA;
    const float* fbB = s_featp + yB*18 + xB;
    const float* fbC = s_featp + yC*18 + xC;
    const float* fbD = s_featp + yD*18 + xD;
    // straddler thread (4p < n0 < 4p+4) uses r=0; its r=1 slots fixed later
    const int rt = (4*p >= n0) ? 1 : 0;

    const unsigned wbU = wsm + (unsigned)cog * 64u + (unsigned)rt * W_R_B;

    unsigned long long acc[4][8];
    #pragma unroll
    for (int i = 0; i < 4; ++i)
        #pragma unroll
        for (int j = 0; j < 8; ++j) acc[i][j] = 0ull;

    // ------------- staging helper (cp.async, zero-fill OOB) -------------
    auto stage_chunk = [&](int cc, int buf) {
        const float* fsrc = feat + ((size_t)(b*CIN + cc*8)) * HW;
        #pragma unroll 1
        for (int i = tid; i < 2592; i += 256) {
            int ci = i / 324, rem = i - ci*324;
            int ly = rem / 18, lx = rem - ly*18;
            int gy = y0 - 1 + ly, gx = x0 - 1 + lx;
            bool v = ((unsigned)gy < 128u) & ((unsigned)gx < 128u);
            const float* src = v ? (fsrc + ci*HW + gy*128 + gx) : fsrc;
            unsigned dst = featsm + (unsigned)buf*FEAT_BUF_B + (unsigned)i*4u;
            asm volatile("cp.async.ca.shared.global [%0], [%1], 4, %2;"
                         :: "r"(dst), "l"(src), "r"(v ? 4 : 0));
        }
        const float4* w0 = (const float4*)(g_kern + ((size_t)(b*2 + 0)*CIN + cc*8)*576);
        const float4* w1 = (const float4*)(g_kern + ((size_t)(b*2 + 1)*CIN + cc*8)*576);
        const unsigned wb = wsm + (unsigned)buf*W_BUF_B;
        #pragma unroll 1
        for (int i = tid; i < 1152; i += 256) {
            asm volatile("cp.async.cg.shared.global [%0], [%1], 16;"
                         :: "r"(wb + (unsigned)i*16u), "l"(w0 + i));
            asm volatile("cp.async.cg.shared.global [%0], [%1], 16;"
                         :: "r"(wb + W_R_B + (unsigned)i*16u), "l"(w1 + i));
        }
        asm volatile("cp.async.commit_group;");
    };

    stage_chunk(0, 0);

    for (int cc = 0; cc < 8; ++cc) {
        const int buf = cc & 1;
        if (cc < 7) {
            stage_chunk(cc + 1, buf ^ 1);
            asm volatile("cp.async.wait_group 1;");
        } else {
            asm volatile("cp.async.wait_group 0;");
        }
        __syncthreads();

        const float* fA = fbA + buf*2592;
        const float* fB = fbB + buf*2592;
        const float* fC = fbC + buf*2592;
        const float* fD = fbD + buf*2592;
        const unsigned wchunk = wbU + (unsigned)buf*W_BUF_B;

        #pragma unroll 1
        for (int ci = 0; ci < 8; ++ci) {
            #pragma unroll
            for (int k = 0; k < 9; ++k) {
                const int ky = k / 3, kx = k - ky*3;
                const int fo = ci*324 + ky*18 + kx;
                float vA = fA[fo], vB = fB[fo], vC = fC[fo], vD = fD[fo];
                unsigned long long pA, pB, pC, pD;
                asm("mov.b64 %0, {%1, %1};" : "=l"(pA) : "f"(vA));
                asm("mov.b64 %0, {%1, %1};" : "=l"(pB) : "f"(vB));
                asm("mov.b64 %0, {%1, %1};" : "=l"(pC) : "f"(vC));
                asm("mov.b64 %0, {%1, %1};" : "=l"(pD) : "f"(vD));
                const unsigned wa = wchunk + (unsigned)(ci*9 + k) * 256u;
                unsigned long long w_[8];
                asm volatile("ld.shared.v2.b64 {%0,%1},[%2];"    : "=l"(w_[0]), "=l"(w_[1]) : "r"(wa));
                asm volatile("ld.shared.v2.b64 {%0,%1},[%2+16];" : "=l"(w_[2]), "=l"(w_[3]) : "r"(wa));
                asm volatile("ld.shared.v2.b64 {%0,%1},[%2+32];" : "=l"(w_[4]), "=l"(w_[5]) : "r"(wa));
                asm volatile("ld.shared.v2.b64 {%0,%1},[%2+48];" : "=l"(w_[6]), "=l"(w_[7]) : "r"(wa));
                #pragma unroll
                for (int q = 0; q < 8; ++q) {
                    asm("fma.rn.f32x2 %0,%1,%2,%0;" : "+l"(acc[0][q]) : "l"(pA), "l"(w_[q]));
                    asm("fma.rn.f32x2 %0,%1,%2,%0;" : "+l"(acc[1][q]) : "l"(pB), "l"(w_[q]));
                    asm("fma.rn.f32x2 %0,%1,%2,%0;" : "+l"(acc[2][q]) : "l"(pC), "l"(w_[q]));
                    asm("fma.rn.f32x2 %0,%1,%2,%0;" : "+l"(acc[3][q]) : "l"(pD), "l"(w_[q]));
                }
            }
        }
        __syncthreads();   // protect buf from next stage overwrite
    }

    // ---- epilogue: write only slots whose r matches rt ----
    const int poff[4] = {(y0+yA)*128 + x0+xA, (y0+yB)*128 + x0+xB,
                         (y0+yC)*128 + x0+xC, (y0+yD)*128 + x0+xD};
    bool wr[4];
    #pragma unroll
    for (int i2 = 0; i2 < 4; ++i2)
        wr[i2] = (((4*p + i2 >= n0) ? 1 : 0) == rt);
    #pragma unroll
    for (int j = 0; j < 8; ++j) {
        const int co = cog*16 + 2*j;
        float* o0 = out + ((size_t)(b*COUT + co)) * HW;
        #pragma unroll
        for (int i2 = 0; i2 < 4; ++i2) {
            if (wr[i2]) {
                float lo, hi;
                asm("mov.b64 {%0,%1},%2;" : "=f"(lo), "=f"(hi) : "l"(acc[i2][j]));
                o0[poff[i2]]      = lo;
                o0[poff[i2] + HW] = hi;
            }
        }
    }

    // ---- fix-up: recompute the <=3 straddler r=1 pixels directly ----
    const int h = n0 & 3;                 // 0 -> no straddler
    if (h && tid < 64*(4 - h)) {
        const int j  = tid >> 6;          // 0..(4-h-1)
        const int co = tid & 63;
        const int id = s_perm[n0 + j];
        const int gy = y0 + (id >> 4), gx = x0 + (id & 15);
        const float* fb = feat + (size_t)b*CIN*HW;
        const float* wb = g_kern + ((size_t)(b*2 + 1))*CIN*576;
        float sum = 0.f;
        #pragma unroll 1
        for (int ci = 0; ci < CIN; ++ci) {
            const float* fp = fb + ci*HW;
            const float* wp = wb + ci*576 + co;
            #pragma unroll
            for (int k = 0; k < 9; ++k) {
                const int ky = k / 3, kx = k - ky*3;
                const int yy = gy + ky - 1, xx = gx + kx - 1;
                float fv = 0.f;
                if ((unsigned)yy < 128u && (unsigned)xx < 128u)
                    fv = fp[yy*128 + xx];
                sum += fv * wp[k*64];
            }
        }
        out[((size_t)(b*COUT + co))*HW + gy*128 + gx] = sum;
    }
}

// ---------------------------------------------------------------------------
// Launch: inputs in metadata order: feat, pred, w1, b1, w2, b2, gk
// ---------------------------------------------------------------------------
#define CONV_DSMEM (2*10368 + 2*36864)   /* 94464 B */

extern "C" void kernel_launch(void* const* d_in, const int* in_sizes, int n_in,
                              void* d_out, int out_size) {
    const float* feat = (const float*)d_in[0];
    const float* pred = (const float*)d_in[1];
    const float* w1   = (const float*)d_in[2];
    const float* b1   = (const float*)d_in[3];
    const float* w2   = (const float*)d_in[4];
    const float* b2   = (const float*)d_in[5];
    const float* gk   = (const float*)d_in[6];
    float* out = (float*)d_out;

    cudaFuncSetAttribute(conv_main_kernel,
                         cudaFuncAttributeMaxDynamicSharedMemorySize, CONV_DSMEM);

    pool_kernel<<<BB*CIN, 128>>>(feat);
    kerngen_kernel<<<BB*RR*9, 256>>>(w1, b1, w2, b2);

    dim3 gsa(4, 4, BB);
    sa_kernel<<<gsa, 256>>>(pred, gk);

    dim3 gc(8, 8, BB);
    conv_main_kernel<<<gc, 256, CONV_DSMEM>>>(feat, pred, out);
}